// round 1
// baseline (speedup 1.0000x reference)
#include <cuda_runtime.h>

#define B_ 2
#define S_ 2048
#define E_ 1024
#define H_ 16
#define D_ 64
#define BH_ (B_ * H_)

// Head-major scratch: [B*H][S][D]
__device__ float g_qh[BH_ * S_ * D_];
__device__ float g_kh[BH_ * S_ * D_];
__device__ float g_vh[BH_ * S_ * D_];

// ---------------------------------------------------------------------------
// Projection GEMM: Y[r,c] = X[r,:] @ W[:,c] + bias[c], written head-major.
// Block tile 128(M) x 64(N), K-tile 16, 256 threads, 8x4 register micro-tile.
// gridDim.z selects which projection (0=q, 1=k, 2=v).
// ---------------------------------------------------------------------------
#define PBM 128
#define PBN 64
#define PBK 16
#define LDA 132   // As row stride (padded, 16B-aligned rows, bank shift 4)
#define LDB 68    // Bs row stride

__global__ __launch_bounds__(256, 2)
void proj_kernel(const float* __restrict__ xq, const float* __restrict__ xk,
                 const float* __restrict__ xv,
                 const float* __restrict__ wq, const float* __restrict__ bq,
                 const float* __restrict__ wk, const float* __restrict__ bk,
                 const float* __restrict__ wv, const float* __restrict__ bv)
{
    __shared__ float As[PBK * LDA];  // transposed: [k][m]
    __shared__ float Bs[PBK * LDB];  // [k][n]

    const int z = blockIdx.z;
    const float* X    = (z == 0) ? xq : (z == 1) ? xk : xv;
    const float* W    = (z == 0) ? wq : (z == 1) ? wk : wv;
    const float* bias = (z == 0) ? bq : (z == 1) ? bk : bv;
    float* dst        = (z == 0) ? g_qh : (z == 1) ? g_kh : g_vh;

    const int tid = threadIdx.x;
    const int tx  = tid & 15;   // n micro index (TN=4 -> 64)
    const int ty  = tid >> 4;   // m micro index (TM=8 -> 128)

    const int m0 = blockIdx.y * PBM;
    const int n0 = blockIdx.x * PBN;

    // loader indices
    const int ar = tid >> 2;          // 0..63  (A row within tile, +64 for 2nd)
    const int ac = (tid & 3) * 4;     // 0,4,8,12 (A k-subcol)
    const int br = tid >> 4;          // 0..15  (B k-row)
    const int bc = (tid & 15) * 4;    // 0..60  (B n-col)

    float acc[8][4];
    #pragma unroll
    for (int i = 0; i < 8; i++)
        #pragma unroll
        for (int j = 0; j < 4; j++) acc[i][j] = 0.f;

    for (int k0 = 0; k0 < E_; k0 += PBK) {
        float4 a0 = *(const float4*)(X + (size_t)(m0 + ar)      * E_ + k0 + ac);
        float4 a1 = *(const float4*)(X + (size_t)(m0 + ar + 64) * E_ + k0 + ac);
        float4 b0 = *(const float4*)(W + (size_t)(k0 + br) * (H_ * D_) + n0 + bc);

        As[(ac + 0) * LDA + ar] = a0.x;
        As[(ac + 1) * LDA + ar] = a0.y;
        As[(ac + 2) * LDA + ar] = a0.z;
        As[(ac + 3) * LDA + ar] = a0.w;
        As[(ac + 0) * LDA + ar + 64] = a1.x;
        As[(ac + 1) * LDA + ar + 64] = a1.y;
        As[(ac + 2) * LDA + ar + 64] = a1.z;
        As[(ac + 3) * LDA + ar + 64] = a1.w;
        *(float4*)(Bs + br * LDB + bc) = b0;
        __syncthreads();

        #pragma unroll
        for (int kk = 0; kk < PBK; kk++) {
            float4 qa = *(const float4*)(As + kk * LDA + ty * 8);
            float4 qb = *(const float4*)(As + kk * LDA + ty * 8 + 4);
            float4 wb = *(const float4*)(Bs + kk * LDB + tx * 4);
            float a[8] = {qa.x, qa.y, qa.z, qa.w, qb.x, qb.y, qb.z, qb.w};
            float b[4] = {wb.x, wb.y, wb.z, wb.w};
            #pragma unroll
            for (int i = 0; i < 8; i++)
                #pragma unroll
                for (int j = 0; j < 4; j++)
                    acc[i][j] += a[i] * b[j];
        }
        __syncthreads();
    }

    // Epilogue: bias add + head-major store. PBN==D so h == blockIdx.x.
    const float4 bv4 = *(const float4*)(bias + n0 + tx * 4);
    const int h = blockIdx.x;
    #pragma unroll
    for (int i = 0; i < 8; i++) {
        int r = m0 + ty * 8 + i;
        int b = r >> 11;        // /2048
        int s = r & 2047;
        float4 o;
        o.x = acc[i][0] + bv4.x;
        o.y = acc[i][1] + bv4.y;
        o.z = acc[i][2] + bv4.z;
        o.w = acc[i][3] + bv4.w;
        *(float4*)(dst + ((size_t)(b * H_ + h) * S_ + s) * D_ + tx * 4) = o;
    }
}

// ---------------------------------------------------------------------------
// Flash-attention fp32: one CTA per (bh, 64-row q-tile), 64-col kv tiles.
// 256 threads, 4x4 micro-tiles for both S=QK^T and O+=PV, online softmax
// with 16-lane xor-shuffle row reductions.
// ---------------------------------------------------------------------------
#define LDS_ 68
#define ATTN_SMEM (4 * 64 * LDS_ * 4)

__global__ __launch_bounds__(256, 2)
void attn_kernel(float* __restrict__ out)
{
    extern __shared__ float sm[];
    float* Qs = sm;                // [d][m]  64 x LDS_
    float* Ks = Qs + 64 * LDS_;    // [d][n]
    float* Vs = Ks + 64 * LDS_;    // [n][dv]
    float* Ps = Vs + 64 * LDS_;    // [n][m]

    const int tid = threadIdx.x;
    const int tx  = tid & 15;
    const int ty  = tid >> 4;
    const int bh  = blockIdx.y;
    const int m0  = blockIdx.x * 64;

    const float* Qp = g_qh + ((size_t)bh * S_ + m0) * D_;
    const float* Kp = g_kh + (size_t)bh * S_ * D_;
    const float* Vp = g_vh + (size_t)bh * S_ * D_;

    const int lr = tid >> 4;          // 0..15 load row
    const int lc = (tid & 15) * 4;    // 0..60 load col

    // Load Q tile transposed into Qs[d][m]
    #pragma unroll
    for (int rr = 0; rr < 64; rr += 16) {
        float4 v = *(const float4*)(Qp + (size_t)(rr + lr) * D_ + lc);
        Qs[(lc + 0) * LDS_ + rr + lr] = v.x;
        Qs[(lc + 1) * LDS_ + rr + lr] = v.y;
        Qs[(lc + 2) * LDS_ + rr + lr] = v.z;
        Qs[(lc + 3) * LDS_ + rr + lr] = v.w;
    }

    float mi[4], li[4], o[4][4];
    #pragma unroll
    for (int i = 0; i < 4; i++) {
        mi[i] = -1e30f;
        li[i] = 0.f;
        #pragma unroll
        for (int j = 0; j < 4; j++) o[i][j] = 0.f;
    }

    const float sc = 0.125f;  // 1/sqrt(64)

    for (int n0 = 0; n0 < S_; n0 += 64) {
        __syncthreads();  // prior PV reads done (also covers Q-load on iter 0)
        #pragma unroll
        for (int rr = 0; rr < 64; rr += 16) {
            float4 kv = *(const float4*)(Kp + (size_t)(n0 + rr + lr) * D_ + lc);
            Ks[(lc + 0) * LDS_ + rr + lr] = kv.x;
            Ks[(lc + 1) * LDS_ + rr + lr] = kv.y;
            Ks[(lc + 2) * LDS_ + rr + lr] = kv.z;
            Ks[(lc + 3) * LDS_ + rr + lr] = kv.w;
            float4 vv = *(const float4*)(Vp + (size_t)(n0 + rr + lr) * D_ + lc);
            *(float4*)(Vs + (rr + lr) * LDS_ + lc) = vv;
        }
        __syncthreads();

        // S = Q @ K^T  (4x4 per thread)
        float s[4][4];
        #pragma unroll
        for (int i = 0; i < 4; i++)
            #pragma unroll
            for (int j = 0; j < 4; j++) s[i][j] = 0.f;

        #pragma unroll 16
        for (int d = 0; d < 64; d++) {
            float4 qa = *(const float4*)(Qs + d * LDS_ + ty * 4);
            float4 kb = *(const float4*)(Ks + d * LDS_ + tx * 4);
            float a[4] = {qa.x, qa.y, qa.z, qa.w};
            float b[4] = {kb.x, kb.y, kb.z, kb.w};
            #pragma unroll
            for (int i = 0; i < 4; i++)
                #pragma unroll
                for (int j = 0; j < 4; j++)
                    s[i][j] += a[i] * b[j];
        }

        // Online softmax per row (rows held across 16 contiguous lanes)
        #pragma unroll
        for (int i = 0; i < 4; i++) {
            float rm = fmaxf(fmaxf(s[i][0], s[i][1]), fmaxf(s[i][2], s[i][3])) * sc;
            #pragma unroll
            for (int w = 8; w >= 1; w >>= 1)
                rm = fmaxf(rm, __shfl_xor_sync(0xffffffffu, rm, w, 16));
            float mnew = fmaxf(mi[i], rm);
            float corr = __expf(mi[i] - mnew);
            mi[i] = mnew;
            float rs = 0.f;
            #pragma unroll
            for (int j = 0; j < 4; j++) {
                float p = __expf(s[i][j] * sc - mnew);
                s[i][j] = p;
                rs += p;
            }
            #pragma unroll
            for (int w = 8; w >= 1; w >>= 1)
                rs += __shfl_xor_sync(0xffffffffu, rs, w, 16);
            li[i] = li[i] * corr + rs;
            #pragma unroll
            for (int j = 0; j < 4; j++) o[i][j] *= corr;
        }

        // Stage P transposed: Ps[n][m]
        #pragma unroll
        for (int j = 0; j < 4; j++)
            #pragma unroll
            for (int i = 0; i < 4; i++)
                Ps[(tx * 4 + j) * LDS_ + ty * 4 + i] = s[i][j];
        __syncthreads();

        // O += P @ V
        #pragma unroll 16
        for (int n = 0; n < 64; n++) {
            float4 pa = *(const float4*)(Ps + n * LDS_ + ty * 4);
            float4 vb = *(const float4*)(Vs + n * LDS_ + tx * 4);
            float a[4] = {pa.x, pa.y, pa.z, pa.w};
            float b[4] = {vb.x, vb.y, vb.z, vb.w};
            #pragma unroll
            for (int i = 0; i < 4; i++)
                #pragma unroll
                for (int j = 0; j < 4; j++)
                    o[i][j] += a[i] * b[j];
        }
    }

    // Epilogue: normalize and write [B, Sq, H*DV]
    const int b = bh >> 4;
    const int h = bh & 15;
    #pragma unroll
    for (int i = 0; i < 4; i++) {
        float inv = 1.f / li[i];
        int srow = m0 + ty * 4 + i;
        float4 ov;
        ov.x = o[i][0] * inv;
        ov.y = o[i][1] * inv;
        ov.z = o[i][2] * inv;
        ov.w = o[i][3] * inv;
        *(float4*)(out + (size_t)(b * S_ + srow) * (H_ * D_) + h * D_ + tx * 4) = ov;
    }
}

// ---------------------------------------------------------------------------
extern "C" void kernel_launch(void* const* d_in, const int* in_sizes, int n_in,
                              void* d_out, int out_size)
{
    (void)in_sizes; (void)n_in; (void)out_size;
    const float* q  = (const float*)d_in[0];
    const float* k  = (const float*)d_in[1];
    const float* v  = (const float*)d_in[2];
    const float* wq = (const float*)d_in[3];
    const float* bq = (const float*)d_in[4];
    const float* wk = (const float*)d_in[5];
    const float* bk = (const float*)d_in[6];
    const float* wv = (const float*)d_in[7];
    const float* bv = (const float*)d_in[8];
    float* out = (float*)d_out;

    dim3 pgrid(H_ * D_ / PBN, (B_ * S_) / PBM, 3);   // (16, 32, 3)
    proj_kernel<<<pgrid, 256>>>(q, k, v, wq, bq, wk, bk, wv, bv);

    cudaFuncSetAttribute(attn_kernel,
                         cudaFuncAttributeMaxDynamicSharedMemorySize, ATTN_SMEM);
    dim3 agrid(S_ / 64, BH_);                        // (32, 32)
    attn_kernel<<<agrid, 256, ATTN_SMEM>>>(out);
}

// round 2
// speedup vs baseline: 2.9274x; 2.9274x over previous
#include <cuda_runtime.h>

#define B_ 2
#define S_ 2048
#define E_ 1024
#define H_ 16
#define D_ 64
#define BH_ (B_ * H_)

// Head-major scratch: [B*H][S][D] fp32
__device__ float g_qh[BH_ * S_ * D_];
__device__ float g_kh[BH_ * S_ * D_];
__device__ float g_vh[BH_ * S_ * D_];

// ---------------------------------------------------------------------------
// helpers: tf32 convert + m16n8k8 tf32 mma
// ---------------------------------------------------------------------------
__device__ __forceinline__ unsigned f2tf(float f) {
    unsigned u;
    asm("cvt.rna.tf32.f32 %0, %1;" : "=r"(u) : "f"(f));
    return u;
}
__device__ __forceinline__ uint4 f2tf4(float4 v) {
    uint4 o;
    o.x = f2tf(v.x); o.y = f2tf(v.y); o.z = f2tf(v.z); o.w = f2tf(v.w);
    return o;
}
__device__ __forceinline__ void mma_tf32(float c[4],
                                         unsigned a0, unsigned a1, unsigned a2, unsigned a3,
                                         unsigned b0, unsigned b1) {
    asm volatile(
        "mma.sync.aligned.m16n8k8.row.col.f32.tf32.tf32.f32 "
        "{%0,%1,%2,%3}, {%4,%5,%6,%7}, {%8,%9}, {%0,%1,%2,%3};"
        : "+f"(c[0]), "+f"(c[1]), "+f"(c[2]), "+f"(c[3])
        : "r"(a0), "r"(a1), "r"(a2), "r"(a3), "r"(b0), "r"(b1));
}

// ---------------------------------------------------------------------------
// Projection GEMM (tf32 tensor): Y = X @ W + bias, head-major output.
// CTA tile 128x64, K-tile 32, 256 threads (8 warps), warp tile 32x32.
// gridDim.z selects projection (0=q,1=k,2=v).
// ---------------------------------------------------------------------------
#define PBM 128
#define PBN 64
#define PBK 32
#define ALD 36   // As row stride (36 % 32 == 4 -> conflict-free frag loads)
#define BLD 72   // Bs row stride (72 % 32 == 8)

__global__ __launch_bounds__(256)
void proj_kernel(const float* __restrict__ xq, const float* __restrict__ xk,
                 const float* __restrict__ xv,
                 const float* __restrict__ wq, const float* __restrict__ bq,
                 const float* __restrict__ wk, const float* __restrict__ bk,
                 const float* __restrict__ wv, const float* __restrict__ bv)
{
    __shared__ unsigned As[PBM * ALD];  // [m][k] tf32 bits
    __shared__ unsigned Bs[PBK * BLD];  // [k][n] tf32 bits

    const int z = blockIdx.z;
    const float* X    = (z == 0) ? xq : (z == 1) ? xk : xv;
    const float* W    = (z == 0) ? wq : (z == 1) ? wk : wv;
    const float* bias = (z == 0) ? bq : (z == 1) ? bk : bv;
    float* dst        = (z == 0) ? g_qh : (z == 1) ? g_kh : g_vh;

    const int tid  = threadIdx.x;
    const int warp = tid >> 5;
    const int lane = tid & 31;
    const int grp  = lane >> 2;  // 0..7
    const int tig  = lane & 3;   // 0..3

    const int wm = (warp & 3) * 32;  // warp row offset
    const int wn = (warp >> 2) * 32; // warp col offset

    const int m0 = blockIdx.y * PBM;
    const int n0 = blockIdx.x * PBN;

    // global-load indices
    const int ar = tid >> 3;          // 0..31 (A row)
    const int ac = (tid & 7) * 4;     // 0..28 (A k col)
    const int br = tid >> 4;          // 0..15 (B k row)
    const int bc = (tid & 15) * 4;    // 0..60 (B n col)

    float acc[2][4][4];
    #pragma unroll
    for (int mt = 0; mt < 2; mt++)
        #pragma unroll
        for (int nt = 0; nt < 4; nt++)
            #pragma unroll
            for (int j = 0; j < 4; j++) acc[mt][nt][j] = 0.f;

    for (int k0 = 0; k0 < E_; k0 += PBK) {
        #pragma unroll
        for (int rr = 0; rr < PBM; rr += 32) {
            float4 a = *(const float4*)(X + (size_t)(m0 + rr + ar) * E_ + k0 + ac);
            *(uint4*)(As + (rr + ar) * ALD + ac) = f2tf4(a);
        }
        #pragma unroll
        for (int kk = 0; kk < PBK; kk += 16) {
            float4 b = *(const float4*)(W + (size_t)(k0 + kk + br) * (H_ * D_) + n0 + bc);
            *(uint4*)(Bs + (kk + br) * BLD + bc) = f2tf4(b);
        }
        __syncthreads();

        #pragma unroll
        for (int ks = 0; ks < 4; ks++) {
            unsigned a[2][4];
            #pragma unroll
            for (int mt = 0; mt < 2; mt++) {
                const unsigned* ap = As + (wm + mt * 16 + grp) * ALD + ks * 8 + tig;
                a[mt][0] = ap[0];
                a[mt][1] = ap[8 * ALD];
                a[mt][2] = ap[4];
                a[mt][3] = ap[8 * ALD + 4];
            }
            unsigned b[4][2];
            #pragma unroll
            for (int nt = 0; nt < 4; nt++) {
                b[nt][0] = Bs[(ks * 8 + tig) * BLD + wn + nt * 8 + grp];
                b[nt][1] = Bs[(ks * 8 + tig + 4) * BLD + wn + nt * 8 + grp];
            }
            #pragma unroll
            for (int mt = 0; mt < 2; mt++)
                #pragma unroll
                for (int nt = 0; nt < 4; nt++)
                    mma_tf32(acc[mt][nt], a[mt][0], a[mt][1], a[mt][2], a[mt][3],
                             b[nt][0], b[nt][1]);
        }
        __syncthreads();
    }

    // Epilogue: bias + head-major store. PBN == D so h == blockIdx.x.
    const int h = blockIdx.x;
    #pragma unroll
    for (int nt = 0; nt < 4; nt++) {
        const int col = wn + nt * 8 + 2 * tig;
        float2 bv2 = *(const float2*)(bias + n0 + col);
        #pragma unroll
        for (int mt = 0; mt < 2; mt++) {
            #pragma unroll
            for (int e = 0; e < 2; e++) {
                int r = m0 + wm + mt * 16 + grp + 8 * e;
                int b = r >> 11;
                int s = r & 2047;
                float2 o;
                o.x = acc[mt][nt][2 * e + 0] + bv2.x;
                o.y = acc[mt][nt][2 * e + 1] + bv2.y;
                *(float2*)(dst + ((size_t)(b * H_ + h) * S_ + s) * D_ + col) = o;
            }
        }
    }
}

// ---------------------------------------------------------------------------
// Flash attention (tf32 tensor): CTA = 64 q-rows of one head, 128 threads.
// Each warp owns 16 q-rows (full softmax rows in-warp). kv tiles of 64.
// ---------------------------------------------------------------------------
#define QLD 68   // 68 % 32 == 4
#define KLD 68
#define VLD 72   // 72 % 32 == 8
#define PLD 68
#define ATTN_SMEM ((64 * QLD + 64 * KLD + 64 * VLD + 64 * PLD) * 4)

__global__ __launch_bounds__(128)
void attn_kernel(float* __restrict__ out)
{
    extern __shared__ unsigned sm[];
    unsigned* Qs = sm;                 // [q][d]
    unsigned* Ks = Qs + 64 * QLD;      // [kv][d]
    unsigned* Vs = Ks + 64 * KLD;      // [kv][d]
    unsigned* Ps = Vs + 64 * VLD;      // [q][kv]

    const int tid  = threadIdx.x;
    const int warp = tid >> 5;   // 0..3
    const int lane = tid & 31;
    const int grp  = lane >> 2;
    const int tig  = lane & 3;
    const int w16  = warp * 16;

    const int bh = blockIdx.y;
    const int m0 = blockIdx.x * 64;

    const float* Qp = g_qh + ((size_t)bh * S_ + m0) * D_;
    const float* Kp = g_kh + (size_t)bh * S_ * D_;
    const float* Vp = g_vh + (size_t)bh * S_ * D_;

    // global loader indices (128 threads, 64x64 tile = 32 elems/thread)
    const int lr = tid >> 4;          // 0..7
    const int lc = (tid & 15) * 4;    // 0..60

    // load Q tile -> Qs (tf32)
    #pragma unroll
    for (int rr = 0; rr < 64; rr += 8) {
        float4 q4 = *(const float4*)(Qp + (size_t)(rr + lr) * D_ + lc);
        *(uint4*)(Qs + (rr + lr) * QLD + lc) = f2tf4(q4);
    }
    __syncthreads();

    // Q A-fragments held in registers for all kv tiles: qa[kstep][4]
    unsigned qa[8][4];
    #pragma unroll
    for (int ks = 0; ks < 8; ks++) {
        const unsigned* qp = Qs + (w16 + grp) * QLD + ks * 8 + tig;
        qa[ks][0] = qp[0];
        qa[ks][1] = qp[8 * QLD];
        qa[ks][2] = qp[4];
        qa[ks][3] = qp[8 * QLD + 4];
    }

    float ofrag[8][4];
    #pragma unroll
    for (int nt = 0; nt < 8; nt++)
        #pragma unroll
        for (int j = 0; j < 4; j++) ofrag[nt][j] = 0.f;

    float mi[2] = {-1e30f, -1e30f};
    float li[2] = {0.f, 0.f};
    const float sc = 0.125f;  // 1/sqrt(64)

    for (int n0 = 0; n0 < S_; n0 += 64) {
        __syncthreads();  // all warps done reading prior Ks/Vs
        #pragma unroll
        for (int rr = 0; rr < 64; rr += 8) {
            float4 k4 = *(const float4*)(Kp + (size_t)(n0 + rr + lr) * D_ + lc);
            *(uint4*)(Ks + (rr + lr) * KLD + lc) = f2tf4(k4);
            float4 v4 = *(const float4*)(Vp + (size_t)(n0 + rr + lr) * D_ + lc);
            *(uint4*)(Vs + (rr + lr) * VLD + lc) = f2tf4(v4);
        }
        __syncthreads();

        // S = Q @ K^T : warp rows w16..w16+15, cols 0..63
        float s[8][4];
        #pragma unroll
        for (int nt = 0; nt < 8; nt++)
            #pragma unroll
            for (int j = 0; j < 4; j++) s[nt][j] = 0.f;

        #pragma unroll
        for (int ks = 0; ks < 8; ks++) {
            #pragma unroll
            for (int nt = 0; nt < 8; nt++) {
                unsigned b0 = Ks[(nt * 8 + grp) * KLD + ks * 8 + tig];
                unsigned b1 = Ks[(nt * 8 + grp) * KLD + ks * 8 + tig + 4];
                mma_tf32(s[nt], qa[ks][0], qa[ks][1], qa[ks][2], qa[ks][3], b0, b1);
            }
        }

        // online softmax: e=0 -> row grp, e=1 -> row grp+8
        #pragma unroll
        for (int e = 0; e < 2; e++) {
            float rm = -1e30f;
            #pragma unroll
            for (int nt = 0; nt < 8; nt++)
                rm = fmaxf(rm, fmaxf(s[nt][2 * e], s[nt][2 * e + 1]));
            rm *= sc;
            rm = fmaxf(rm, __shfl_xor_sync(0xffffffffu, rm, 1, 4));
            rm = fmaxf(rm, __shfl_xor_sync(0xffffffffu, rm, 2, 4));
            float mnew = fmaxf(mi[e], rm);
            float corr = __expf(mi[e] - mnew);
            mi[e] = mnew;
            float rs = 0.f;
            #pragma unroll
            for (int nt = 0; nt < 8; nt++) {
                float p0 = __expf(s[nt][2 * e] * sc - mnew);
                float p1 = __expf(s[nt][2 * e + 1] * sc - mnew);
                s[nt][2 * e] = p0;
                s[nt][2 * e + 1] = p1;
                rs += p0 + p1;
            }
            rs += __shfl_xor_sync(0xffffffffu, rs, 1, 4);
            rs += __shfl_xor_sync(0xffffffffu, rs, 2, 4);
            li[e] = li[e] * corr + rs;
            #pragma unroll
            for (int nt = 0; nt < 8; nt++) {
                ofrag[nt][2 * e]     *= corr;
                ofrag[nt][2 * e + 1] *= corr;
            }
        }

        // stage P (tf32) into per-warp-private smem rows
        #pragma unroll
        for (int nt = 0; nt < 8; nt++) {
            #pragma unroll
            for (int e = 0; e < 2; e++) {
                uint2 pv;
                pv.x = f2tf(s[nt][2 * e]);
                pv.y = f2tf(s[nt][2 * e + 1]);
                *(uint2*)(Ps + (w16 + grp + 8 * e) * PLD + nt * 8 + 2 * tig) = pv;
            }
        }
        __syncwarp();

        // O += P @ V
        #pragma unroll
        for (int ks = 0; ks < 8; ks++) {
            const unsigned* pp = Ps + (w16 + grp) * PLD + ks * 8 + tig;
            unsigned pa0 = pp[0];
            unsigned pa1 = pp[8 * PLD];
            unsigned pa2 = pp[4];
            unsigned pa3 = pp[8 * PLD + 4];
            #pragma unroll
            for (int nt = 0; nt < 8; nt++) {
                unsigned vb0 = Vs[(ks * 8 + tig) * VLD + nt * 8 + grp];
                unsigned vb1 = Vs[(ks * 8 + tig + 4) * VLD + nt * 8 + grp];
                mma_tf32(ofrag[nt], pa0, pa1, pa2, pa3, vb0, vb1);
            }
        }
    }

    // epilogue: normalize, write [B, Sq, H*DV]
    const int b = bh >> 4;
    const int h = bh & 15;
    #pragma unroll
    for (int e = 0; e < 2; e++) {
        float inv = 1.f / li[e];
        int srow = m0 + w16 + grp + 8 * e;
        float* orow = out + (size_t)(b * S_ + srow) * (H_ * D_) + h * D_;
        #pragma unroll
        for (int nt = 0; nt < 8; nt++) {
            float2 ov;
            ov.x = ofrag[nt][2 * e] * inv;
            ov.y = ofrag[nt][2 * e + 1] * inv;
            *(float2*)(orow + nt * 8 + 2 * tig) = ov;
        }
    }
}

// ---------------------------------------------------------------------------
extern "C" void kernel_launch(void* const* d_in, const int* in_sizes, int n_in,
                              void* d_out, int out_size)
{
    (void)in_sizes; (void)n_in; (void)out_size;
    const float* q  = (const float*)d_in[0];
    const float* k  = (const float*)d_in[1];
    const float* v  = (const float*)d_in[2];
    const float* wq = (const float*)d_in[3];
    const float* bq = (const float*)d_in[4];
    const float* wk = (const float*)d_in[5];
    const float* bk = (const float*)d_in[6];
    const float* wv = (const float*)d_in[7];
    const float* bv = (const float*)d_in[8];
    float* out = (float*)d_out;

    dim3 pgrid(H_ * D_ / PBN, (B_ * S_) / PBM, 3);   // (16, 32, 3)
    proj_kernel<<<pgrid, 256>>>(q, k, v, wq, bq, wk, bk, wv, bv);

    cudaFuncSetAttribute(attn_kernel,
                         cudaFuncAttributeMaxDynamicSharedMemorySize, ATTN_SMEM);
    dim3 agrid(S_ / 64, BH_);                        // (32, 32)
    attn_kernel<<<agrid, 128, ATTN_SMEM>>>(out);
}

// round 3
// speedup vs baseline: 3.2378x; 1.1060x over previous
#include <cuda_runtime.h>

#define B_ 2
#define S_ 2048
#define E_ 1024
#define H_ 16
#define D_ 64
#define BH_ (B_ * H_)

// Head-major scratch: [B*H][S][D] fp32
__device__ float g_qh[BH_ * S_ * D_];
__device__ float g_kh[BH_ * S_ * D_];
__device__ float g_vh[BH_ * S_ * D_];

// ---------------------------------------------------------------------------
// helpers
// ---------------------------------------------------------------------------
__device__ __forceinline__ unsigned f2tf(float f) {
    unsigned u;
    asm("cvt.rna.tf32.f32 %0, %1;" : "=r"(u) : "f"(f));
    return u;
}
__device__ __forceinline__ uint4 f2tf4(float4 v) {
    uint4 o;
    o.x = f2tf(v.x); o.y = f2tf(v.y); o.z = f2tf(v.z); o.w = f2tf(v.w);
    return o;
}
__device__ __forceinline__ void mma_tf32(float c[4],
                                         unsigned a0, unsigned a1, unsigned a2, unsigned a3,
                                         unsigned b0, unsigned b1) {
    asm volatile(
        "mma.sync.aligned.m16n8k8.row.col.f32.tf32.tf32.f32 "
        "{%0,%1,%2,%3}, {%4,%5,%6,%7}, {%8,%9}, {%0,%1,%2,%3};"
        : "+f"(c[0]), "+f"(c[1]), "+f"(c[2]), "+f"(c[3])
        : "r"(a0), "r"(a1), "r"(a2), "r"(a3), "r"(b0), "r"(b1));
}
__device__ __forceinline__ void cp16(void* dst, const void* src) {
    unsigned d = (unsigned)__cvta_generic_to_shared(dst);
    asm volatile("cp.async.cg.shared.global [%0], [%1], 16;" :: "r"(d), "l"(src));
}
__device__ __forceinline__ void cp_commit() {
    asm volatile("cp.async.commit_group;");
}
template <int N>
__device__ __forceinline__ void cp_wait() {
    asm volatile("cp.async.wait_group %0;" :: "n"(N));
}

// ---------------------------------------------------------------------------
// Projection GEMM (tf32 tensor, cp.async 2-stage pipeline)
// CTA tile 128x128, K-tile 32, 256 threads (8 warps), warp tile 64x32.
// smem holds RAW fp32; cvt to tf32 at fragment-load time (rna rounding kept).
// gridDim.z selects projection (0=q,1=k,2=v).
// ---------------------------------------------------------------------------
#define PBM 128
#define PBN 128
#define PBK 32
#define ALD 36    // 36 % 32 == 4  -> conflict-free A-frag loads
#define BLD 136   // 136 % 32 == 8 -> conflict-free B-frag loads
#define ASZ (PBM * ALD)
#define BSZ (PBK * BLD)
#define PROJ_SMEM (2 * (ASZ + BSZ) * 4)

__global__ __launch_bounds__(256, 2)
void proj_kernel(const float* __restrict__ xq, const float* __restrict__ xk,
                 const float* __restrict__ xv,
                 const float* __restrict__ wq, const float* __restrict__ bq,
                 const float* __restrict__ wk, const float* __restrict__ bk,
                 const float* __restrict__ wv, const float* __restrict__ bv)
{
    extern __shared__ float psm[];
    float* As = psm;                 // [2][PBM][ALD] raw fp32
    float* Bs = psm + 2 * ASZ;       // [2][PBK][BLD]

    const int z = blockIdx.z;
    const float* X    = (z == 0) ? xq : (z == 1) ? xk : xv;
    const float* W    = (z == 0) ? wq : (z == 1) ? wk : wv;
    const float* bias = (z == 0) ? bq : (z == 1) ? bk : bv;
    float* dst        = (z == 0) ? g_qh : (z == 1) ? g_kh : g_vh;

    const int tid  = threadIdx.x;
    const int warp = tid >> 5;
    const int lane = tid & 31;
    const int grp  = lane >> 2;
    const int tig  = lane & 3;

    const int wm = (warp & 1) * 64;   // warp row offset (2 warps in M)
    const int wn = (warp >> 1) * 32;  // warp col offset (4 warps in N)

    const int m0 = blockIdx.y * PBM;
    const int n0 = blockIdx.x * PBN;

    float acc[4][4][4];
    #pragma unroll
    for (int mt = 0; mt < 4; mt++)
        #pragma unroll
        for (int nt = 0; nt < 4; nt++)
            #pragma unroll
            for (int j = 0; j < 4; j++) acc[mt][nt][j] = 0.f;

    // async stage of k-tile kt into buffer buf
    auto issue = [&](int kt, int buf) {
        float* Ab = As + buf * ASZ;
        float* Bb = Bs + buf * BSZ;
        #pragma unroll
        for (int it = 0; it < 4; it++) {
            int id = tid + it * 256;            // 0..1023
            int r  = id >> 3;                   // 0..127
            int c4 = (id & 7) * 4;              // 0..28
            cp16(Ab + r * ALD + c4, X + (size_t)(m0 + r) * E_ + kt * PBK + c4);
        }
        #pragma unroll
        for (int it = 0; it < 4; it++) {
            int id = tid + it * 256;
            int r  = id >> 5;                   // 0..31
            int c4 = (id & 31) * 4;             // 0..124
            cp16(Bb + r * BLD + c4, W + (size_t)(kt * PBK + r) * (H_ * D_) + n0 + c4);
        }
        cp_commit();
    };

    issue(0, 0);

    const int NT = E_ / PBK;  // 32
    for (int kt = 0; kt < NT; kt++) {
        if (kt + 1 < NT) {
            issue(kt + 1, (kt + 1) & 1);
            cp_wait<1>();
        } else {
            cp_wait<0>();
        }
        __syncthreads();

        const float* Ab = As + (kt & 1) * ASZ;
        const float* Bb = Bs + (kt & 1) * BSZ;

        #pragma unroll
        for (int ks = 0; ks < 4; ks++) {
            unsigned a[4][4];
            #pragma unroll
            for (int mt = 0; mt < 4; mt++) {
                const float* ap = Ab + (wm + mt * 16 + grp) * ALD + ks * 8 + tig;
                a[mt][0] = f2tf(ap[0]);
                a[mt][1] = f2tf(ap[8 * ALD]);
                a[mt][2] = f2tf(ap[4]);
                a[mt][3] = f2tf(ap[8 * ALD + 4]);
            }
            unsigned b[4][2];
            #pragma unroll
            for (int nt = 0; nt < 4; nt++) {
                b[nt][0] = f2tf(Bb[(ks * 8 + tig) * BLD + wn + nt * 8 + grp]);
                b[nt][1] = f2tf(Bb[(ks * 8 + tig + 4) * BLD + wn + nt * 8 + grp]);
            }
            #pragma unroll
            for (int mt = 0; mt < 4; mt++)
                #pragma unroll
                for (int nt = 0; nt < 4; nt++)
                    mma_tf32(acc[mt][nt], a[mt][0], a[mt][1], a[mt][2], a[mt][3],
                             b[nt][0], b[nt][1]);
        }
        __syncthreads();
    }

    // Epilogue: bias + head-major store [B*H][S][D]
    #pragma unroll
    for (int nt = 0; nt < 4; nt++) {
        const int ng = n0 + wn + nt * 8 + 2 * tig;  // global col
        const int h  = ng >> 6;
        const int d  = ng & 63;
        float2 bv2 = *(const float2*)(bias + ng);
        #pragma unroll
        for (int mt = 0; mt < 4; mt++) {
            #pragma unroll
            for (int e = 0; e < 2; e++) {
                int r = m0 + wm + mt * 16 + grp + 8 * e;
                int b = r >> 11;
                int s = r & 2047;
                float2 o;
                o.x = acc[mt][nt][2 * e + 0] + bv2.x;
                o.y = acc[mt][nt][2 * e + 1] + bv2.y;
                *(float2*)(dst + ((size_t)(b * H_ + h) * S_ + s) * D_ + d) = o;
            }
        }
    }
}

// ---------------------------------------------------------------------------
// Flash attention (tf32 tensor): CTA = 64 q-rows of one head, 128 threads.
// P-staging buffer overlays the (dead) Q smem tile -> 53.2KB -> 4 CTAs/SM.
// ---------------------------------------------------------------------------
#define QLD 68   // 68 % 32 == 4
#define KLD 68
#define VLD 72   // 72 % 32 == 8
#define ATTN_SMEM ((64 * QLD + 64 * KLD + 64 * VLD) * 4)

__global__ __launch_bounds__(128, 4)
void attn_kernel(float* __restrict__ out)
{
    extern __shared__ unsigned sm[];
    unsigned* Qs = sm;                 // [q][d]  -- becomes Ps after prologue
    unsigned* Ks = Qs + 64 * QLD;      // [kv][d]
    unsigned* Vs = Ks + 64 * KLD;      // [kv][d]
    unsigned* Ps = Qs;                 // overlay

    const int tid  = threadIdx.x;
    const int warp = tid >> 5;
    const int lane = tid & 31;
    const int grp  = lane >> 2;
    const int tig  = lane & 3;
    const int w16  = warp * 16;

    const int bh = blockIdx.y;
    const int m0 = blockIdx.x * 64;

    const float* Qp = g_qh + ((size_t)bh * S_ + m0) * D_;
    const float* Kp = g_kh + (size_t)bh * S_ * D_;
    const float* Vp = g_vh + (size_t)bh * S_ * D_;

    const int lr = tid >> 4;          // 0..7
    const int lc = (tid & 15) * 4;    // 0..60

    // prologue: load Q tile -> smem -> registers (A-fragments)
    #pragma unroll
    for (int rr = 0; rr < 64; rr += 8) {
        float4 q4 = *(const float4*)(Qp + (size_t)(rr + lr) * D_ + lc);
        *(uint4*)(Qs + (rr + lr) * QLD + lc) = f2tf4(q4);
    }
    __syncthreads();

    unsigned qa[8][4];
    #pragma unroll
    for (int ks = 0; ks < 8; ks++) {
        const unsigned* qp = Qs + (w16 + grp) * QLD + ks * 8 + tig;
        qa[ks][0] = qp[0];
        qa[ks][1] = qp[8 * QLD];
        qa[ks][2] = qp[4];
        qa[ks][3] = qp[8 * QLD + 4];
    }

    float ofrag[8][4];
    #pragma unroll
    for (int nt = 0; nt < 8; nt++)
        #pragma unroll
        for (int j = 0; j < 4; j++) ofrag[nt][j] = 0.f;

    float mi[2] = {-1e30f, -1e30f};
    float li[2] = {0.f, 0.f};
    const float sc = 0.125f;  // 1/sqrt(64)

    for (int n0 = 0; n0 < S_; n0 += 64) {
        __syncthreads();  // prior tile fully consumed (and qa extraction done)
        #pragma unroll
        for (int rr = 0; rr < 64; rr += 8) {
            float4 k4 = *(const float4*)(Kp + (size_t)(n0 + rr + lr) * D_ + lc);
            *(uint4*)(Ks + (rr + lr) * KLD + lc) = f2tf4(k4);
            float4 v4 = *(const float4*)(Vp + (size_t)(n0 + rr + lr) * D_ + lc);
            *(uint4*)(Vs + (rr + lr) * VLD + lc) = f2tf4(v4);
        }
        __syncthreads();

        // S = Q @ K^T
        float s[8][4];
        #pragma unroll
        for (int nt = 0; nt < 8; nt++)
            #pragma unroll
            for (int j = 0; j < 4; j++) s[nt][j] = 0.f;

        #pragma unroll
        for (int ks = 0; ks < 8; ks++) {
            #pragma unroll
            for (int nt = 0; nt < 8; nt++) {
                unsigned b0 = Ks[(nt * 8 + grp) * KLD + ks * 8 + tig];
                unsigned b1 = Ks[(nt * 8 + grp) * KLD + ks * 8 + tig + 4];
                mma_tf32(s[nt], qa[ks][0], qa[ks][1], qa[ks][2], qa[ks][3], b0, b1);
            }
        }

        // online softmax (rows live within 4-lane groups)
        #pragma unroll
        for (int e = 0; e < 2; e++) {
            float rm = -1e30f;
            #pragma unroll
            for (int nt = 0; nt < 8; nt++)
                rm = fmaxf(rm, fmaxf(s[nt][2 * e], s[nt][2 * e + 1]));
            rm *= sc;
            rm = fmaxf(rm, __shfl_xor_sync(0xffffffffu, rm, 1, 4));
            rm = fmaxf(rm, __shfl_xor_sync(0xffffffffu, rm, 2, 4));
            float mnew = fmaxf(mi[e], rm);
            float corr = __expf(mi[e] - mnew);
            mi[e] = mnew;
            float rs = 0.f;
            #pragma unroll
            for (int nt = 0; nt < 8; nt++) {
                float p0 = __expf(s[nt][2 * e] * sc - mnew);
                float p1 = __expf(s[nt][2 * e + 1] * sc - mnew);
                s[nt][2 * e] = p0;
                s[nt][2 * e + 1] = p1;
                rs += p0 + p1;
            }
            rs += __shfl_xor_sync(0xffffffffu, rs, 1, 4);
            rs += __shfl_xor_sync(0xffffffffu, rs, 2, 4);
            li[e] = li[e] * corr + rs;
            #pragma unroll
            for (int nt = 0; nt < 8; nt++) {
                ofrag[nt][2 * e]     *= corr;
                ofrag[nt][2 * e + 1] *= corr;
            }
        }

        // stage P (tf32) into per-warp-private rows of the overlay buffer
        #pragma unroll
        for (int nt = 0; nt < 8; nt++) {
            #pragma unroll
            for (int e = 0; e < 2; e++) {
                uint2 pv;
                pv.x = f2tf(s[nt][2 * e]);
                pv.y = f2tf(s[nt][2 * e + 1]);
                *(uint2*)(Ps + (w16 + grp + 8 * e) * QLD + nt * 8 + 2 * tig) = pv;
            }
        }
        __syncwarp();

        // O += P @ V
        #pragma unroll
        for (int ks = 0; ks < 8; ks++) {
            const unsigned* pp = Ps + (w16 + grp) * QLD + ks * 8 + tig;
            unsigned pa0 = pp[0];
            unsigned pa1 = pp[8 * QLD];
            unsigned pa2 = pp[4];
            unsigned pa3 = pp[8 * QLD + 4];
            #pragma unroll
            for (int nt = 0; nt < 8; nt++) {
                unsigned vb0 = Vs[(ks * 8 + tig) * VLD + nt * 8 + grp];
                unsigned vb1 = Vs[(ks * 8 + tig + 4) * VLD + nt * 8 + grp];
                mma_tf32(ofrag[nt], pa0, pa1, pa2, pa3, vb0, vb1);
            }
        }
    }

    // epilogue: normalize, write [B, Sq, H*DV]
    const int b = bh >> 4;
    const int h = bh & 15;
    #pragma unroll
    for (int e = 0; e < 2; e++) {
        float inv = 1.f / li[e];
        int srow = m0 + w16 + grp + 8 * e;
        float* orow = out + (size_t)(b * S_ + srow) * (H_ * D_) + h * D_;
        #pragma unroll
        for (int nt = 0; nt < 8; nt++) {
            float2 ov;
            ov.x = ofrag[nt][2 * e] * inv;
            ov.y = ofrag[nt][2 * e + 1] * inv;
            *(float2*)(orow + nt * 8 + 2 * tig) = ov;
        }
    }
}

// ---------------------------------------------------------------------------
extern "C" void kernel_launch(void* const* d_in, const int* in_sizes, int n_in,
                              void* d_out, int out_size)
{
    (void)in_sizes; (void)n_in; (void)out_size;
    const float* q  = (const float*)d_in[0];
    const float* k  = (const float*)d_in[1];
    const float* v  = (const float*)d_in[2];
    const float* wq = (const float*)d_in[3];
    const float* bq = (const float*)d_in[4];
    const float* wk = (const float*)d_in[5];
    const float* bk = (const float*)d_in[6];
    const float* wv = (const float*)d_in[7];
    const float* bv = (const float*)d_in[8];
    float* out = (float*)d_out;

    cudaFuncSetAttribute(proj_kernel,
                         cudaFuncAttributeMaxDynamicSharedMemorySize, PROJ_SMEM);
    dim3 pgrid(H_ * D_ / PBN, (B_ * S_) / PBM, 3);   // (8, 32, 3)
    proj_kernel<<<pgrid, 256, PROJ_SMEM>>>(q, k, v, wq, bq, wk, bk, wv, bv);

    cudaFuncSetAttribute(attn_kernel,
                         cudaFuncAttributeMaxDynamicSharedMemorySize, ATTN_SMEM);
    dim3 agrid(S_ / 64, BH_);                        // (32, 32)
    attn_kernel<<<agrid, 128, ATTN_SMEM>>>(out);
}

// round 4
// speedup vs baseline: 4.8664x; 1.5030x over previous
#include <cuda_runtime.h>
#include <cuda_fp16.h>

#define B_ 2
#define S_ 2048
#define E_ 1024
#define H_ 16
#define D_ 64
#define BH_ (B_ * H_)

// Head-major scratch: [B*H][S][D] fp16
__device__ __half g_qh[BH_ * S_ * D_];
__device__ __half g_kh[BH_ * S_ * D_];
__device__ __half g_vh[BH_ * S_ * D_];

// ---------------------------------------------------------------------------
// helpers
// ---------------------------------------------------------------------------
__device__ __forceinline__ unsigned f2tf(float f) {
    unsigned u;
    asm("cvt.rna.tf32.f32 %0, %1;" : "=r"(u) : "f"(f));
    return u;
}
__device__ __forceinline__ void mma_tf32(float c[4],
                                         unsigned a0, unsigned a1, unsigned a2, unsigned a3,
                                         unsigned b0, unsigned b1) {
    asm volatile(
        "mma.sync.aligned.m16n8k8.row.col.f32.tf32.tf32.f32 "
        "{%0,%1,%2,%3}, {%4,%5,%6,%7}, {%8,%9}, {%0,%1,%2,%3};"
        : "+f"(c[0]), "+f"(c[1]), "+f"(c[2]), "+f"(c[3])
        : "r"(a0), "r"(a1), "r"(a2), "r"(a3), "r"(b0), "r"(b1));
}
__device__ __forceinline__ void mma_f16(float c[4],
                                        unsigned a0, unsigned a1, unsigned a2, unsigned a3,
                                        unsigned b0, unsigned b1) {
    asm volatile(
        "mma.sync.aligned.m16n8k16.row.col.f32.f16.f16.f32 "
        "{%0,%1,%2,%3}, {%4,%5,%6,%7}, {%8,%9}, {%0,%1,%2,%3};"
        : "+f"(c[0]), "+f"(c[1]), "+f"(c[2]), "+f"(c[3])
        : "r"(a0), "r"(a1), "r"(a2), "r"(a3), "r"(b0), "r"(b1));
}
__device__ __forceinline__ void ldsm4(unsigned& r0, unsigned& r1, unsigned& r2, unsigned& r3,
                                      unsigned addr) {
    asm volatile("ldmatrix.sync.aligned.m8n8.x4.shared.b16 {%0,%1,%2,%3}, [%4];"
                 : "=r"(r0), "=r"(r1), "=r"(r2), "=r"(r3) : "r"(addr));
}
__device__ __forceinline__ void ldsm4t(unsigned& r0, unsigned& r1, unsigned& r2, unsigned& r3,
                                       unsigned addr) {
    asm volatile("ldmatrix.sync.aligned.m8n8.x4.trans.shared.b16 {%0,%1,%2,%3}, [%4];"
                 : "=r"(r0), "=r"(r1), "=r"(r2), "=r"(r3) : "r"(addr));
}
__device__ __forceinline__ void cp16(void* dst, const void* src) {
    unsigned d = (unsigned)__cvta_generic_to_shared(dst);
    asm volatile("cp.async.cg.shared.global [%0], [%1], 16;" :: "r"(d), "l"(src));
}
__device__ __forceinline__ void cp_commit() { asm volatile("cp.async.commit_group;"); }
template <int N>
__device__ __forceinline__ void cp_wait() {
    asm volatile("cp.async.wait_group %0;" :: "n"(N));
}

// ---------------------------------------------------------------------------
// Projection GEMM (tf32 tensor, cp.async 2-stage pipeline), fp16 output.
// CTA tile 128x128, K-tile 32, 256 threads, warp tile 64x32.
// ---------------------------------------------------------------------------
#define PBM 128
#define PBN 128
#define PBK 32
#define ALD 36
#define BLD 136
#define ASZ (PBM * ALD)
#define BSZ (PBK * BLD)
#define PROJ_SMEM (2 * (ASZ + BSZ) * 4)

__global__ __launch_bounds__(256, 2)
void proj_kernel(const float* __restrict__ xq, const float* __restrict__ xk,
                 const float* __restrict__ xv,
                 const float* __restrict__ wq, const float* __restrict__ bq,
                 const float* __restrict__ wk, const float* __restrict__ bk,
                 const float* __restrict__ wv, const float* __restrict__ bv)
{
    extern __shared__ float psm[];
    float* As = psm;
    float* Bs = psm + 2 * ASZ;

    const int z = blockIdx.z;
    const float* X    = (z == 0) ? xq : (z == 1) ? xk : xv;
    const float* W    = (z == 0) ? wq : (z == 1) ? wk : wv;
    const float* bias = (z == 0) ? bq : (z == 1) ? bk : bv;
    __half* dst       = (z == 0) ? g_qh : (z == 1) ? g_kh : g_vh;

    const int tid  = threadIdx.x;
    const int warp = tid >> 5;
    const int lane = tid & 31;
    const int grp  = lane >> 2;
    const int tig  = lane & 3;

    const int wm = (warp & 1) * 64;
    const int wn = (warp >> 1) * 32;

    const int m0 = blockIdx.y * PBM;
    const int n0 = blockIdx.x * PBN;

    float acc[4][4][4];
    #pragma unroll
    for (int mt = 0; mt < 4; mt++)
        #pragma unroll
        for (int nt = 0; nt < 4; nt++)
            #pragma unroll
            for (int j = 0; j < 4; j++) acc[mt][nt][j] = 0.f;

    auto issue = [&](int kt, int buf) {
        float* Ab = As + buf * ASZ;
        float* Bb = Bs + buf * BSZ;
        #pragma unroll
        for (int it = 0; it < 4; it++) {
            int id = tid + it * 256;
            int r  = id >> 3;
            int c4 = (id & 7) * 4;
            cp16(Ab + r * ALD + c4, X + (size_t)(m0 + r) * E_ + kt * PBK + c4);
        }
        #pragma unroll
        for (int it = 0; it < 4; it++) {
            int id = tid + it * 256;
            int r  = id >> 5;
            int c4 = (id & 31) * 4;
            cp16(Bb + r * BLD + c4, W + (size_t)(kt * PBK + r) * (H_ * D_) + n0 + c4);
        }
        cp_commit();
    };

    issue(0, 0);

    const int NT = E_ / PBK;
    for (int kt = 0; kt < NT; kt++) {
        if (kt + 1 < NT) {
            issue(kt + 1, (kt + 1) & 1);
            cp_wait<1>();
        } else {
            cp_wait<0>();
        }
        __syncthreads();

        const float* Ab = As + (kt & 1) * ASZ;
        const float* Bb = Bs + (kt & 1) * BSZ;

        #pragma unroll
        for (int ks = 0; ks < 4; ks++) {
            unsigned a[4][4];
            #pragma unroll
            for (int mt = 0; mt < 4; mt++) {
                const float* ap = Ab + (wm + mt * 16 + grp) * ALD + ks * 8 + tig;
                a[mt][0] = f2tf(ap[0]);
                a[mt][1] = f2tf(ap[8 * ALD]);
                a[mt][2] = f2tf(ap[4]);
                a[mt][3] = f2tf(ap[8 * ALD + 4]);
            }
            unsigned b[4][2];
            #pragma unroll
            for (int nt = 0; nt < 4; nt++) {
                b[nt][0] = f2tf(Bb[(ks * 8 + tig) * BLD + wn + nt * 8 + grp]);
                b[nt][1] = f2tf(Bb[(ks * 8 + tig + 4) * BLD + wn + nt * 8 + grp]);
            }
            #pragma unroll
            for (int mt = 0; mt < 4; mt++)
                #pragma unroll
                for (int nt = 0; nt < 4; nt++)
                    mma_tf32(acc[mt][nt], a[mt][0], a[mt][1], a[mt][2], a[mt][3],
                             b[nt][0], b[nt][1]);
        }
        __syncthreads();
    }

    // Epilogue: bias + head-major fp16 store [B*H][S][D]
    #pragma unroll
    for (int nt = 0; nt < 4; nt++) {
        const int ng = n0 + wn + nt * 8 + 2 * tig;
        const int h  = ng >> 6;
        const int d  = ng & 63;
        float2 bv2 = *(const float2*)(bias + ng);
        #pragma unroll
        for (int mt = 0; mt < 4; mt++) {
            #pragma unroll
            for (int e = 0; e < 2; e++) {
                int r = m0 + wm + mt * 16 + grp + 8 * e;
                int b = r >> 11;
                int s = r & 2047;
                __half2 o = __floats2half2_rn(acc[mt][nt][2 * e + 0] + bv2.x,
                                              acc[mt][nt][2 * e + 1] + bv2.y);
                *(__half2*)(dst + ((size_t)(b * H_ + h) * S_ + s) * D_ + d) = o;
            }
        }
    }
}

// ---------------------------------------------------------------------------
// Flash attention, fp16 mma m16n8k16 + ldmatrix operand loads.
// CTA = 64 q-rows of one head, 128 threads; P overlays dead Q smem.
// ---------------------------------------------------------------------------
#define LD_ 72   // row stride in halves (144B; 144 % 128 == 16 -> ldsm conflict-free)

__global__ __launch_bounds__(128, 4)
void attn_kernel(float* __restrict__ out)
{
    __shared__ __half hsm[3 * 64 * LD_];
    __half* Qs = hsm;                 // [q][d]   (reused as Ps[q][kv])
    __half* Ks = hsm + 64 * LD_;      // [kv][d]
    __half* Vs = hsm + 2 * 64 * LD_;  // [kv][d]
    __half* Ps = Qs;

    const unsigned qs_base = (unsigned)__cvta_generic_to_shared(Qs);
    const unsigned ks_base = (unsigned)__cvta_generic_to_shared(Ks);
    const unsigned vs_base = (unsigned)__cvta_generic_to_shared(Vs);

    const int tid  = threadIdx.x;
    const int warp = tid >> 5;
    const int lane = tid & 31;
    const int grp  = lane >> 2;
    const int tig  = lane & 3;
    const int w16  = warp * 16;

    const int bh = blockIdx.y;
    const int m0 = blockIdx.x * 64;

    const __half* Qp = g_qh + ((size_t)bh * S_ + m0) * D_;
    const __half* Kp = g_kh + (size_t)bh * S_ * D_;
    const __half* Vp = g_vh + (size_t)bh * S_ * D_;

    // tile loader: 64 rows x 64 halves; each thread 4x uint4 (8 halves)
    const int lr = tid >> 3;          // 0..15
    const int lc = (tid & 7) * 8;     // 0..56 (halves)

    // prologue: Q tile -> smem
    #pragma unroll
    for (int rr = 0; rr < 64; rr += 16)
        *(uint4*)(Qs + (rr + lr) * LD_ + lc) =
            *(const uint4*)(Qp + (size_t)(rr + lr) * D_ + lc);
    __syncthreads();

    // Q A-fragments (all 4 k-steps) into registers via ldmatrix.x4
    unsigned qa[4][4];
    #pragma unroll
    for (int ks = 0; ks < 4; ks++) {
        unsigned addr = qs_base +
            ((w16 + (lane & 15)) * LD_ + ks * 16 + (lane >> 4) * 8) * 2;
        ldsm4(qa[ks][0], qa[ks][1], qa[ks][2], qa[ks][3], addr);
    }

    float ofrag[8][4];
    #pragma unroll
    for (int nt = 0; nt < 8; nt++)
        #pragma unroll
        for (int j = 0; j < 4; j++) ofrag[nt][j] = 0.f;

    float mi[2] = {-1e30f, -1e30f};
    float li[2] = {0.f, 0.f};
    const float sc2 = 0.125f * 1.4426950408889634f;  // 1/sqrt(64) * log2(e)

    for (int n0 = 0; n0 < S_; n0 += 64) {
        __syncthreads();
        #pragma unroll
        for (int rr = 0; rr < 64; rr += 16) {
            *(uint4*)(Ks + (rr + lr) * LD_ + lc) =
                *(const uint4*)(Kp + (size_t)(n0 + rr + lr) * D_ + lc);
            *(uint4*)(Vs + (rr + lr) * LD_ + lc) =
                *(const uint4*)(Vp + (size_t)(n0 + rr + lr) * D_ + lc);
        }
        __syncthreads();

        // S = Q @ K^T
        float s[8][4];
        #pragma unroll
        for (int nt = 0; nt < 8; nt++)
            #pragma unroll
            for (int j = 0; j < 4; j++) s[nt][j] = 0.f;

        #pragma unroll
        for (int ks = 0; ks < 4; ks++) {
            #pragma unroll
            for (int ntp = 0; ntp < 4; ntp++) {
                unsigned b0, b1, b2, b3;
                unsigned kaddr = ks_base +
                    ((ntp * 16 + ((lane >> 4) & 1) * 8 + (lane & 7)) * LD_ +
                     ks * 16 + ((lane >> 3) & 1) * 8) * 2;
                ldsm4(b0, b1, b2, b3, kaddr);
                mma_f16(s[2 * ntp],     qa[ks][0], qa[ks][1], qa[ks][2], qa[ks][3], b0, b1);
                mma_f16(s[2 * ntp + 1], qa[ks][0], qa[ks][1], qa[ks][2], qa[ks][3], b2, b3);
            }
        }

        // online softmax in log2 domain
        #pragma unroll
        for (int e = 0; e < 2; e++) {
            float rm = -1e30f;
            #pragma unroll
            for (int nt = 0; nt < 8; nt++)
                rm = fmaxf(rm, fmaxf(s[nt][2 * e], s[nt][2 * e + 1]));
            rm *= sc2;
            rm = fmaxf(rm, __shfl_xor_sync(0xffffffffu, rm, 1, 4));
            rm = fmaxf(rm, __shfl_xor_sync(0xffffffffu, rm, 2, 4));
            float mnew = fmaxf(mi[e], rm);
            float corr = exp2f(mi[e] - mnew);
            mi[e] = mnew;
            float rs = 0.f;
            #pragma unroll
            for (int nt = 0; nt < 8; nt++) {
                float p0 = exp2f(s[nt][2 * e] * sc2 - mnew);
                float p1 = exp2f(s[nt][2 * e + 1] * sc2 - mnew);
                s[nt][2 * e] = p0;
                s[nt][2 * e + 1] = p1;
                rs += p0 + p1;
            }
            rs += __shfl_xor_sync(0xffffffffu, rs, 1, 4);
            rs += __shfl_xor_sync(0xffffffffu, rs, 2, 4);
            li[e] = li[e] * corr + rs;
            #pragma unroll
            for (int nt = 0; nt < 8; nt++) {
                ofrag[nt][2 * e]     *= corr;
                ofrag[nt][2 * e + 1] *= corr;
            }
        }

        // stage P (fp16) into per-warp-private overlay rows
        #pragma unroll
        for (int nt = 0; nt < 8; nt++) {
            #pragma unroll
            for (int e = 0; e < 2; e++) {
                *(__half2*)(Ps + (w16 + grp + 8 * e) * LD_ + nt * 8 + 2 * tig) =
                    __floats2half2_rn(s[nt][2 * e], s[nt][2 * e + 1]);
            }
        }
        __syncwarp();

        // O += P @ V  (V fragments via ldmatrix.trans, no transpose staging)
        #pragma unroll
        for (int ks = 0; ks < 4; ks++) {
            unsigned p0, p1, p2, p3;
            unsigned paddr = qs_base +
                ((w16 + (lane & 15)) * LD_ + ks * 16 + (lane >> 4) * 8) * 2;
            ldsm4(p0, p1, p2, p3, paddr);
            #pragma unroll
            for (int ntp = 0; ntp < 4; ntp++) {
                unsigned v0, v1, v2, v3;
                unsigned vaddr = vs_base +
                    ((ks * 16 + (lane & 15)) * LD_ +
                     ntp * 16 + ((lane >> 4) & 1) * 8) * 2;
                ldsm4t(v0, v1, v2, v3, vaddr);
                mma_f16(ofrag[2 * ntp],     p0, p1, p2, p3, v0, v1);
                mma_f16(ofrag[2 * ntp + 1], p0, p1, p2, p3, v2, v3);
            }
        }
    }

    // epilogue: normalize, write [B, Sq, H*DV] fp32
    const int b = bh >> 4;
    const int h = bh & 15;
    #pragma unroll
    for (int e = 0; e < 2; e++) {
        float inv = 1.f / li[e];
        int srow = m0 + w16 + grp + 8 * e;
        float* orow = out + (size_t)(b * S_ + srow) * (H_ * D_) + h * D_;
        #pragma unroll
        for (int nt = 0; nt < 8; nt++) {
            float2 ov;
            ov.x = ofrag[nt][2 * e] * inv;
            ov.y = ofrag[nt][2 * e + 1] * inv;
            *(float2*)(orow + nt * 8 + 2 * tig) = ov;
        }
    }
}

// ---------------------------------------------------------------------------
extern "C" void kernel_launch(void* const* d_in, const int* in_sizes, int n_in,
                              void* d_out, int out_size)
{
    (void)in_sizes; (void)n_in; (void)out_size;
    const float* q  = (const float*)d_in[0];
    const float* k  = (const float*)d_in[1];
    const float* v  = (const float*)d_in[2];
    const float* wq = (const float*)d_in[3];
    const float* bq = (const float*)d_in[4];
    const float* wk = (const float*)d_in[5];
    const float* bk = (const float*)d_in[6];
    const float* wv = (const float*)d_in[7];
    const float* bv = (const float*)d_in[8];
    float* out = (float*)d_out;

    cudaFuncSetAttribute(proj_kernel,
                         cudaFuncAttributeMaxDynamicSharedMemorySize, PROJ_SMEM);
    dim3 pgrid(H_ * D_ / PBN, (B_ * S_) / PBM, 3);   // (8, 32, 3)
    proj_kernel<<<pgrid, 256, PROJ_SMEM>>>(q, k, v, wq, bq, wk, bk, wv, bv);

    dim3 agrid(S_ / 64, BH_);                        // (32, 32)
    attn_kernel<<<agrid, 128>>>(out);
}